// round 1
// baseline (speedup 1.0000x reference)
#include <cuda_runtime.h>
#include <cfloat>
#include <cstdint>

// ---------------- scratch (__device__ globals; no allocations) ----------------
__device__ float g_qkv[1024 * 3072];              // 12 MB  (T, 3C)
__device__ float g_att[16 * 1024 * 1024];         // 64 MB  (H, T, T)
__device__ float g_scores[16 * 1024 * 8192];      // 512 MB (H, T, M)
__device__ float g_ksnorm[16 * 8192];             // (H, M)
__device__ int   g_idx[16 * 1024 * 4];            // (H, T, 4)
__device__ int   g_sel[16 * 1024];                // (H, T)
__device__ float g_vnew[16 * 1024 * 64];          // (H, T, d)
__device__ float g_y[1024 * 1024];                // (T, C)

// ---------------- generic 128x128x8 SGEMM: C = epilogue(A * B^T) ----------------
// A: (M,K) row-major w/ row stride lda, B: (N,K) row-major w/ row stride ldb.
// MODE 0: + bias(aux[col]);  MODE 1: * 0.125, skip blocks fully above causal diag;
// MODE 2: aux[col] - 2*acc  (kNN squared-distance score, const ||k||^2 dropped).
template <int MODE>
__global__ void gemm128(const float* __restrict__ A, int lda, long long aZ,
                        const float* __restrict__ B, int ldb, long long bZ,
                        float* __restrict__ C, int ldc, long long cZ,
                        int K, const float* __restrict__ aux, long long auxZ) {
    int bx = blockIdx.x, by = blockIdx.y, z = blockIdx.z;
    if (MODE == 1 && bx > by) return;  // tile fully above causal diagonal
    A += (size_t)z * aZ + (size_t)by * 128 * lda;
    B += (size_t)z * bZ + (size_t)bx * 128 * ldb;
    C += (size_t)z * cZ;
    if (MODE != 1) aux += (size_t)z * auxZ;

    __shared__ float As[8][128];
    __shared__ float Bs[8][128];

    int tid = threadIdx.x;
    int tx = tid & 15, ty = tid >> 4;
    int lr = tid >> 1, lc = (tid & 1) * 4;

    float acc[8][8];
#pragma unroll
    for (int i = 0; i < 8; i++)
#pragma unroll
        for (int j = 0; j < 8; j++) acc[i][j] = 0.f;

    const float* Ap = A + (size_t)lr * lda + lc;
    const float* Bp = B + (size_t)lr * ldb + lc;

    for (int k0 = 0; k0 < K; k0 += 8) {
        float4 a4 = *(const float4*)(Ap + k0);
        float4 b4 = *(const float4*)(Bp + k0);
        __syncthreads();
        As[lc + 0][lr] = a4.x; As[lc + 1][lr] = a4.y;
        As[lc + 2][lr] = a4.z; As[lc + 3][lr] = a4.w;
        Bs[lc + 0][lr] = b4.x; Bs[lc + 1][lr] = b4.y;
        Bs[lc + 2][lr] = b4.z; Bs[lc + 3][lr] = b4.w;
        __syncthreads();
#pragma unroll
        for (int kk = 0; kk < 8; kk++) {
            float a[8], b[8];
#pragma unroll
            for (int i = 0; i < 8; i++) a[i] = As[kk][ty * 8 + i];
#pragma unroll
            for (int j = 0; j < 8; j++) b[j] = Bs[kk][tx * 8 + j];
#pragma unroll
            for (int i = 0; i < 8; i++)
#pragma unroll
                for (int j = 0; j < 8; j++) acc[i][j] = fmaf(a[i], b[j], acc[i][j]);
        }
    }

#pragma unroll
    for (int i = 0; i < 8; i++) {
        int row = by * 128 + ty * 8 + i;
#pragma unroll
        for (int j = 0; j < 8; j++) {
            int col = bx * 128 + tx * 8 + j;
            float v = acc[i][j];
            if (MODE == 0) v += aux[col];
            if (MODE == 1) v *= 0.125f;                 // 1/sqrt(64)
            if (MODE == 2) v = aux[col] - 2.0f * v;     // d2 (minus const term)
            C[(size_t)row * ldc + col] = v;
        }
    }
}

// ---------------- ||key_store[h,m]||^2 ----------------
__global__ void ksnorm_kernel(const float* __restrict__ ks, float* __restrict__ nrm) {
    int r = blockIdx.x * blockDim.x + threadIdx.x;
    if (r >= 16 * 8192) return;
    const float4* p = (const float4*)(ks + (size_t)r * 64);
    float s = 0.f;
#pragma unroll
    for (int i = 0; i < 16; i++) {
        float4 f = p[i];
        s += f.x * f.x + f.y * f.y + f.z * f.z + f.w * f.w;
    }
    nrm[r] = s;
}

// ---------------- causal row softmax (in place), zero strictly-upper part ----------------
__global__ void softmax_kernel(float* __restrict__ att) {
    int t = blockIdx.x, h = blockIdx.y;
    float* row = att + ((size_t)h * 1024 + t) * 1024;
    int tid = threadIdx.x;
    int lane = tid & 31, warp = tid >> 5;
    int n = t + 1;

    __shared__ float red[8];
    __shared__ float bcast;

    float m = -FLT_MAX;
    for (int k = tid; k < n; k += 256) m = fmaxf(m, row[k]);
#pragma unroll
    for (int o = 16; o > 0; o >>= 1) m = fmaxf(m, __shfl_xor_sync(0xffffffffu, m, o));
    if (lane == 0) red[warp] = m;
    __syncthreads();
    if (tid == 0) {
        float v = red[0];
#pragma unroll
        for (int w = 1; w < 8; w++) v = fmaxf(v, red[w]);
        bcast = v;
    }
    __syncthreads();
    m = bcast;

    float s = 0.f;
    for (int k = tid; k < n; k += 256) s += expf(row[k] - m);
#pragma unroll
    for (int o = 16; o > 0; o >>= 1) s += __shfl_xor_sync(0xffffffffu, s, o);
    if (lane == 0) red[warp] = s;
    __syncthreads();
    if (tid == 0) {
        float v = 0.f;
#pragma unroll
        for (int w = 0; w < 8; w++) v += red[w];
        bcast = v;
    }
    __syncthreads();
    float inv = 1.f / bcast;

    for (int k = tid; k < n; k += 256) row[k] = expf(row[k] - m) * inv;
    for (int k = n + tid; k < 1024; k += 256) row[k] = 0.f;
}

// ---------------- sel[h,t] = att[h, T-1, t] >= 1/(MEM_FRAC*T) ----------------
__global__ void sel_kernel(const float* __restrict__ att, int* __restrict__ sel) {
    int i = blockIdx.x * 256 + threadIdx.x;  // < 16384
    int h = i >> 10, t = i & 1023;
    float a = att[((size_t)h * 1024 + 1023) * 1024 + t];
    sel[i] = (a >= (1.0f / 8192.0f)) ? 1 : 0;
}

// ---------------- top-4 smallest per score row (stable: ties -> lower index) --------
__device__ __forceinline__ bool lex_lt(float sa, int ia, float sb, int ib) {
    return sa < sb || (sa == sb && ia < ib);
}

__global__ void topk_kernel(const float* __restrict__ scores, int* __restrict__ idx_out) {
    int row = blockIdx.x;  // h*1024 + t
    const float* s = scores + (size_t)row * 8192;
    int tid = threadIdx.x;

    float b0 = FLT_MAX, b1 = FLT_MAX, b2 = FLT_MAX, b3 = FLT_MAX;
    int i0 = 0x7fffffff, i1 = 0x7fffffff, i2 = 0x7fffffff, i3 = 0x7fffffff;

    for (int m = tid; m < 8192; m += 256) {
        float v = s[m];
        if (lex_lt(v, m, b3, i3)) {
            if (lex_lt(v, m, b2, i2)) {
                b3 = b2; i3 = i2;
                if (lex_lt(v, m, b1, i1)) {
                    b2 = b1; i2 = i1;
                    if (lex_lt(v, m, b0, i0)) { b1 = b0; i1 = i0; b0 = v; i0 = m; }
                    else                      { b1 = v; i1 = m; }
                } else { b2 = v; i2 = m; }
            } else { b3 = v; i3 = m; }
        }
    }

    __shared__ float ss[256][4];
    __shared__ int   si[256][4];
    ss[tid][0] = b0; ss[tid][1] = b1; ss[tid][2] = b2; ss[tid][3] = b3;
    si[tid][0] = i0; si[tid][1] = i1; si[tid][2] = i2; si[tid][3] = i3;
    __syncthreads();

    for (int st = 128; st >= 1; st >>= 1) {
        if (tid < st) {
            float as[4], os[4], rs[4];
            int   ai[4], oi[4], ri[4];
#pragma unroll
            for (int k = 0; k < 4; k++) {
                as[k] = ss[tid][k];      ai[k] = si[tid][k];
                os[k] = ss[tid + st][k]; oi[k] = si[tid + st][k];
            }
            int a = 0, b = 0;
#pragma unroll
            for (int k = 0; k < 4; k++) {
                bool ta = lex_lt(as[a], ai[a], os[b], oi[b]);
                rs[k] = ta ? as[a] : os[b];
                ri[k] = ta ? ai[a] : oi[b];
                if (ta) a++; else b++;
            }
#pragma unroll
            for (int k = 0; k < 4; k++) { ss[tid][k] = rs[k]; si[tid][k] = ri[k]; }
        }
        __syncthreads();
    }
    if (tid < 4) idx_out[(size_t)row * 4 + tid] = si[0][tid];
}

// ---------------- per-token 5-way memory softmax & blend -> v_new ----------------
__device__ __forceinline__ float warp_sum(float v) {
#pragma unroll
    for (int o = 16; o > 0; o >>= 1) v += __shfl_xor_sync(0xffffffffu, v, o);
    return v;
}

__global__ void vnew_kernel(const float* __restrict__ qkv, const float* __restrict__ kstore,
                            const float* __restrict__ vstore, const int* __restrict__ idx,
                            const int* __restrict__ sel, float* __restrict__ vnew) {
    int gw = (blockIdx.x * blockDim.x + threadIdx.x) >> 5;
    int lane = threadIdx.x & 31;
    if (gw >= 16 * 1024) return;
    int h = gw >> 10, t = gw & 1023;

    const float* base = qkv + (size_t)t * 3072 + h * 64;
    int d0 = lane * 2;
    float q0 = base[d0],        q1 = base[d0 + 1];
    float k0 = base[1024 + d0], k1 = base[1024 + d0 + 1];
    float v0 = base[2048 + d0], v1 = base[2048 + d0 + 1];
    const float scale = 0.125f;

    float attf[5];
    attf[0] = warp_sum(q0 * k0 + q1 * k1) * scale;

    int ids[4];
#pragma unroll
    for (int s2 = 0; s2 < 4; s2++) ids[s2] = idx[(size_t)gw * 4 + s2];

    float fv0[4], fv1[4];
#pragma unroll
    for (int s2 = 0; s2 < 4; s2++) {
        const float* kp = kstore + ((size_t)h * 8192 + ids[s2]) * 64;
        attf[s2 + 1] = warp_sum(q0 * kp[d0] + q1 * kp[d0 + 1]) * scale;
        const float* vp = vstore + ((size_t)h * 8192 + ids[s2]) * 64;
        fv0[s2] = vp[d0]; fv1[s2] = vp[d0 + 1];
    }

    float mx = attf[0];
#pragma unroll
    for (int s2 = 1; s2 < 5; s2++) mx = fmaxf(mx, attf[s2]);
    float e[5], sum = 0.f;
#pragma unroll
    for (int s2 = 0; s2 < 5; s2++) { e[s2] = expf(attf[s2] - mx); sum += e[s2]; }
    float inv = 1.f / sum;

    float o0 = e[0] * v0, o1 = e[0] * v1;
#pragma unroll
    for (int s2 = 0; s2 < 4; s2++) { o0 += e[s2 + 1] * fv0[s2]; o1 += e[s2 + 1] * fv1[s2]; }
    o0 = o0 * inv * 0.5f + v0 * 0.5f;   // RESID_FOUND=RESID_CURR=0.5
    o1 = o1 * inv * 0.5f + v1 * 0.5f;

    bool sl = sel[gw] != 0;
    vnew[(size_t)gw * 64 + d0]     = sl ? o0 : v0;
    vnew[(size_t)gw * 64 + d0 + 1] = sl ? o1 : v1;
}

// ---------------- y = att @ v_new  (per head, N=64), writes (T,C) layout ----------------
__global__ void ygemm_kernel(const float* __restrict__ att, const float* __restrict__ vnew,
                             float* __restrict__ y) {
    int h = blockIdx.y, t0 = blockIdx.x * 128;
    __shared__ float As[16][132];  // [k][t], padded
    __shared__ float Bs[16][64];   // [k][dd]
    int tid = threadIdx.x;
    int tx = tid & 7, ty = tid >> 3;  // tx: 8 groups of 8 dd; ty: 32 groups of 4 t

    float acc[4][8];
#pragma unroll
    for (int i = 0; i < 4; i++)
#pragma unroll
        for (int j = 0; j < 8; j++) acc[i][j] = 0.f;

    const float* Ab = att + ((size_t)h * 1024 + t0) * 1024;
    const float* Bb = vnew + (size_t)h * 1024 * 64;

    int r = tid >> 2, c = (tid & 3) * 4;          // att loader
    int rb = tid >> 4, cb = (tid & 15) * 4;       // vnew loader

    for (int k0 = 0; k0 < 1024; k0 += 16) {
        float4 fa0 = *(const float4*)(Ab + (size_t)r * 1024 + k0 + c);
        float4 fa1 = *(const float4*)(Ab + (size_t)(r + 64) * 1024 + k0 + c);
        float4 fb  = *(const float4*)(Bb + (size_t)(k0 + rb) * 64 + cb);
        __syncthreads();
        As[c + 0][r] = fa0.x; As[c + 1][r] = fa0.y; As[c + 2][r] = fa0.z; As[c + 3][r] = fa0.w;
        As[c + 0][r + 64] = fa1.x; As[c + 1][r + 64] = fa1.y;
        As[c + 2][r + 64] = fa1.z; As[c + 3][r + 64] = fa1.w;
        *(float4*)&Bs[rb][cb] = fb;
        __syncthreads();
#pragma unroll
        for (int kk = 0; kk < 16; kk++) {
            float a[4], b[8];
#pragma unroll
            for (int i = 0; i < 4; i++) a[i] = As[kk][ty * 4 + i];
#pragma unroll
            for (int j = 0; j < 8; j++) b[j] = Bs[kk][tx * 8 + j];
#pragma unroll
            for (int i = 0; i < 4; i++)
#pragma unroll
                for (int j = 0; j < 8; j++) acc[i][j] = fmaf(a[i], b[j], acc[i][j]);
        }
    }

#pragma unroll
    for (int i = 0; i < 4; i++)
#pragma unroll
        for (int j = 0; j < 8; j++)
            y[(size_t)(t0 + ty * 4 + i) * 1024 + h * 64 + tx * 8 + j] = acc[i][j];
}

// ---------------- launch ----------------
extern "C" void kernel_launch(void* const* d_in, const int* in_sizes, int n_in,
                              void* d_out, int out_size) {
    const float* x  = (const float*)d_in[0];
    const float* aw = (const float*)d_in[1];
    const float* ab = (const float*)d_in[2];
    const float* pw = (const float*)d_in[3];
    const float* pb = (const float*)d_in[4];
    const float* ks = (const float*)d_in[5];
    const float* vs = (const float*)d_in[6];
    float* out = (float*)d_out;

    float *qkv, *att, *scores, *ksn, *vnw, *y;
    int *idx, *sel;
    cudaGetSymbolAddress((void**)&qkv,    g_qkv);
    cudaGetSymbolAddress((void**)&att,    g_att);
    cudaGetSymbolAddress((void**)&scores, g_scores);
    cudaGetSymbolAddress((void**)&ksn,    g_ksnorm);
    cudaGetSymbolAddress((void**)&idx,    g_idx);
    cudaGetSymbolAddress((void**)&sel,    g_sel);
    cudaGetSymbolAddress((void**)&vnw,    g_vnew);
    cudaGetSymbolAddress((void**)&y,      g_y);

    // 1) qkv = x @ c_attn_w^T + b    (M=1024, N=3072, K=1024)
    gemm128<0><<<dim3(24, 8, 1), 256>>>(x, 1024, 0, aw, 1024, 0,
                                        qkv, 3072, 0, 1024, ab, 0);
    // 2) ||key_store||^2 per (h,m)
    ksnorm_kernel<<<512, 256>>>(ks, ksn);
    // 3) logits = q k^T / 8  (per head, causal tiles only)
    gemm128<1><<<dim3(8, 8, 16), 256>>>(qkv, 3072, 64, qkv + 1024, 3072, 64,
                                        att, 1024, 1024LL * 1024, 64, nullptr, 0);
    // 4) causal softmax in place
    softmax_kernel<<<dim3(1024, 16), 256>>>(att);
    // 5) sel from last row
    sel_kernel<<<64, 256>>>(att, sel);
    // 6) kNN scores = ||ks||^2 - 2 k·ks^T  (per head, M=1024, N=8192, K=64)
    gemm128<2><<<dim3(64, 8, 16), 256>>>(qkv + 1024, 3072, 64, ks, 64, 8192LL * 64,
                                         scores, 8192, 1024LL * 8192, 64, ksn, 8192);
    // 7) top-4 per row
    topk_kernel<<<16384, 256>>>(scores, idx);
    // 8) 5-way softmax blend -> v_new
    vnew_kernel<<<2048, 256>>>(qkv, ks, vs, idx, sel, vnw);
    // 9) y = att @ v_new (per head), (T,C) layout
    ygemm_kernel<<<dim3(8, 16), 256>>>(att, vnw, y);
    // 10) out = y @ c_proj_w^T + b
    gemm128<0><<<dim3(8, 8, 1), 256>>>(y, 1024, 0, pw, 1024, 0,
                                       out, 1024, 0, 1024, pb, 0);
}

// round 2
// speedup vs baseline: 1.1183x; 1.1183x over previous
#include <cuda_runtime.h>
#include <cfloat>
#include <cstdint>

// ---------------- scratch (__device__ globals; no allocations) ----------------
__device__ float g_qkv[1024 * 3072];              // 12 MB  (T, 3C)
__device__ float g_att[16 * 1024 * 1024];         // 64 MB  (H, T, T)
__device__ float g_ksnorm[16 * 8192];             // (H, M)
__device__ int   g_idx[16 * 1024 * 4];            // (H, T, 4)
__device__ int   g_sel[16 * 1024];                // (H, T)
__device__ float g_vnew[16 * 1024 * 64];          // (H, T, d)
__device__ float g_y[1024 * 1024];                // (T, C)

// ---------------- generic 128x128x16 SGEMM: C = epilogue(A * B^T) ----------------
// A: (M,K) row-major w/ row stride lda, B: (N,K) row-major w/ row stride ldb.
// MODE 0: + bias(aux[col]);  MODE 1: * 0.125, skip blocks fully above causal diag.
template <int MODE>
__global__ void gemm128(const float* __restrict__ A, int lda, long long aZ,
                        const float* __restrict__ B, int ldb, long long bZ,
                        float* __restrict__ C, int ldc, long long cZ,
                        int K, const float* __restrict__ aux, long long auxZ) {
    int bx = blockIdx.x, by = blockIdx.y, z = blockIdx.z;
    if (MODE == 1 && bx > by) return;  // tile fully above causal diagonal
    A += (size_t)z * aZ + (size_t)by * 128 * lda;
    B += (size_t)z * bZ + (size_t)bx * 128 * ldb;
    C += (size_t)z * cZ;
    if (MODE != 1) aux += (size_t)z * auxZ;

    __shared__ float As[16][128];
    __shared__ float Bs[16][128];

    int tid = threadIdx.x;
    int tx = tid & 15, ty = tid >> 4;
    int lr = tid >> 1, lc = (tid & 1) * 4;

    float acc[8][8];
#pragma unroll
    for (int i = 0; i < 8; i++)
#pragma unroll
        for (int j = 0; j < 8; j++) acc[i][j] = 0.f;

    const float* Ap = A + (size_t)lr * lda + lc;
    const float* Bp = B + (size_t)lr * ldb + lc;

    for (int k0 = 0; k0 < K; k0 += 16) {
        float4 a0 = *(const float4*)(Ap + k0);
        float4 a1 = *(const float4*)(Ap + k0 + 8);
        float4 b0 = *(const float4*)(Bp + k0);
        float4 b1 = *(const float4*)(Bp + k0 + 8);
        __syncthreads();
        As[lc + 0][lr] = a0.x; As[lc + 1][lr] = a0.y;
        As[lc + 2][lr] = a0.z; As[lc + 3][lr] = a0.w;
        As[lc + 8][lr] = a1.x; As[lc + 9][lr] = a1.y;
        As[lc + 10][lr] = a1.z; As[lc + 11][lr] = a1.w;
        Bs[lc + 0][lr] = b0.x; Bs[lc + 1][lr] = b0.y;
        Bs[lc + 2][lr] = b0.z; Bs[lc + 3][lr] = b0.w;
        Bs[lc + 8][lr] = b1.x; Bs[lc + 9][lr] = b1.y;
        Bs[lc + 10][lr] = b1.z; Bs[lc + 11][lr] = b1.w;
        __syncthreads();
#pragma unroll
        for (int kk = 0; kk < 16; kk++) {
            float a[8], b[8];
#pragma unroll
            for (int i = 0; i < 8; i++) a[i] = As[kk][ty * 8 + i];
#pragma unroll
            for (int j = 0; j < 8; j++) b[j] = Bs[kk][tx * 8 + j];
#pragma unroll
            for (int i = 0; i < 8; i++)
#pragma unroll
                for (int j = 0; j < 8; j++) acc[i][j] = fmaf(a[i], b[j], acc[i][j]);
        }
    }

#pragma unroll
    for (int i = 0; i < 8; i++) {
        int row = by * 128 + ty * 8 + i;
#pragma unroll
        for (int j = 0; j < 8; j++) {
            int col = bx * 128 + tx * 8 + j;
            float v = acc[i][j];
            if (MODE == 0) v += aux[col];
            if (MODE == 1) v *= 0.125f;                 // 1/sqrt(64)
            C[(size_t)row * ldc + col] = v;
        }
    }
}

// ---------------- ||key_store[h,m]||^2 ----------------
__global__ void ksnorm_kernel(const float* __restrict__ ks, float* __restrict__ nrm) {
    int r = blockIdx.x * blockDim.x + threadIdx.x;
    if (r >= 16 * 8192) return;
    const float4* p = (const float4*)(ks + (size_t)r * 64);
    float s = 0.f;
#pragma unroll
    for (int i = 0; i < 16; i++) {
        float4 f = p[i];
        s += f.x * f.x + f.y * f.y + f.z * f.z + f.w * f.w;
    }
    nrm[r] = s;
}

// ---------------- causal row softmax (in place), zero strictly-upper part ----------------
__global__ void softmax_kernel(float* __restrict__ att) {
    int t = blockIdx.x, h = blockIdx.y;
    float* row = att + ((size_t)h * 1024 + t) * 1024;
    int tid = threadIdx.x;
    int lane = tid & 31, warp = tid >> 5;
    int n = t + 1;

    __shared__ float red[8];
    __shared__ float bcast;

    float m = -FLT_MAX;
    for (int k = tid; k < n; k += 256) m = fmaxf(m, row[k]);
#pragma unroll
    for (int o = 16; o > 0; o >>= 1) m = fmaxf(m, __shfl_xor_sync(0xffffffffu, m, o));
    if (lane == 0) red[warp] = m;
    __syncthreads();
    if (tid == 0) {
        float v = red[0];
#pragma unroll
        for (int w = 1; w < 8; w++) v = fmaxf(v, red[w]);
        bcast = v;
    }
    __syncthreads();
    m = bcast;

    float s = 0.f;
    for (int k = tid; k < n; k += 256) s += expf(row[k] - m);
#pragma unroll
    for (int o = 16; o > 0; o >>= 1) s += __shfl_xor_sync(0xffffffffu, s, o);
    if (lane == 0) red[warp] = s;
    __syncthreads();
    if (tid == 0) {
        float v = 0.f;
#pragma unroll
        for (int w = 0; w < 8; w++) v += red[w];
        bcast = v;
    }
    __syncthreads();
    float inv = 1.f / bcast;

    for (int k = tid; k < n; k += 256) row[k] = expf(row[k] - m) * inv;
    for (int k = n + tid; k < 1024; k += 256) row[k] = 0.f;
}

// ---------------- sel[h,t] = att[h, T-1, t] >= 1/(MEM_FRAC*T) ----------------
__global__ void sel_kernel(const float* __restrict__ att, int* __restrict__ sel) {
    int i = blockIdx.x * 256 + threadIdx.x;  // < 16384
    int h = i >> 10, t = i & 1023;
    float a = att[((size_t)h * 1024 + 1023) * 1024 + t];
    sel[i] = (a >= (1.0f / 8192.0f)) ? 1 : 0;
}

// ---------------- lexicographic (score, idx) compare: stable top-k semantics --------
__device__ __forceinline__ bool lex_lt(float sa, int ia, float sb, int ib) {
    return sa < sb || (sa == sb && ia < ib);
}

#define TOP4_INSERT(v, m, s0, x0, s1, x1, s2, x2, s3, x3)              \
    if (lex_lt(v, m, s3, x3)) {                                        \
        if (lex_lt(v, m, s2, x2)) {                                    \
            s3 = s2; x3 = x2;                                          \
            if (lex_lt(v, m, s1, x1)) {                                \
                s2 = s1; x2 = x1;                                      \
                if (lex_lt(v, m, s0, x0)) {                            \
                    s1 = s0; x1 = x0; s0 = v; x0 = m;                  \
                } else { s1 = v; x1 = m; }                             \
            } else { s2 = v; x2 = m; }                                 \
        } else { s3 = v; x3 = m; }                                     \
    }

// ---------------- fused kNN scores + top-4 (streams M, never spills scores) --------
// Block: 256 threads, 64 t-rows x one head; loops over M=8192 in 128-wide chunks.
// score[t][m] = ||ks_m||^2 - 2 * k_t . ks_m   (const ||k_t||^2 dropped; ordering same)
// smem (dynamic): As[64][68] (k-major A), Bs[64][132] (k-major B chunk), Ns[128]
#define KNN_AS_STRIDE 68
#define KNN_BS_STRIDE 132
#define KNN_SMEM_FLOATS (64 * KNN_AS_STRIDE + 64 * KNN_BS_STRIDE + 128)

__global__ __launch_bounds__(256) void knn_topk_kernel(
    const float* __restrict__ qkv, const float* __restrict__ kstore,
    const float* __restrict__ ksn, int* __restrict__ idx_out) {
    extern __shared__ float sm[];
    float* As = sm;                                   // [64][68]  k-major
    float* Bs = sm + 64 * KNN_AS_STRIDE;              // [64][132] k-major
    float* Ns = Bs + 64 * KNN_BS_STRIDE;              // [128]

    const int tid = threadIdx.x;
    const int t0 = blockIdx.x * 64;
    const int h = blockIdx.y;
    const int tx = tid & 15;       // 16 col groups of 8
    const int ty = tid >> 4;       // 16 row groups of 4

    // Load A once: k-vectors of 64 t-rows, transposed to [k][t].
    // lanes vary along t (r) -> conflict-free transposed stores.
    const float* Abase = qkv + (size_t)t0 * 3072 + 1024 + h * 64;
    for (int i = tid; i < 64 * 16; i += 256) {
        int r = i & 63, c4 = (i >> 6) << 2;
        float4 v = *(const float4*)(Abase + (size_t)r * 3072 + c4);
        As[(c4 + 0) * KNN_AS_STRIDE + r] = v.x;
        As[(c4 + 1) * KNN_AS_STRIDE + r] = v.y;
        As[(c4 + 2) * KNN_AS_STRIDE + r] = v.z;
        As[(c4 + 3) * KNN_AS_STRIDE + r] = v.w;
    }

    // Per-thread running top-4 for each of this thread's 4 rows.
    float s0[4], s1[4], s2[4], s3[4];
    int x0[4], x1[4], x2[4], x3[4];
#pragma unroll
    for (int i = 0; i < 4; i++) {
        s0[i] = s1[i] = s2[i] = s3[i] = FLT_MAX;
        x0[i] = x1[i] = x2[i] = x3[i] = 0x7fffffff;
    }

    const float* Bbase = kstore + (size_t)h * 8192 * 64;
    const float* Nbase = ksn + h * 8192;

    for (int chunk = 0; chunk < 64; chunk++) {
        const int m0 = chunk << 7;
        __syncthreads();  // previous compute done before overwriting Bs/Ns
        if (tid < 128) Ns[tid] = Nbase[m0 + tid];
        for (int i = tid; i < 128 * 16; i += 256) {
            int r = i & 127, c4 = (i >> 7) << 2;
            float4 v = *(const float4*)(Bbase + (size_t)(m0 + r) * 64 + c4);
            Bs[(c4 + 0) * KNN_BS_STRIDE + r] = v.x;
            Bs[(c4 + 1) * KNN_BS_STRIDE + r] = v.y;
            Bs[(c4 + 2) * KNN_BS_STRIDE + r] = v.z;
            Bs[(c4 + 3) * KNN_BS_STRIDE + r] = v.w;
        }
        __syncthreads();

        float acc[4][8];
#pragma unroll
        for (int i = 0; i < 4; i++)
#pragma unroll
            for (int j = 0; j < 8; j++) acc[i][j] = 0.f;

#pragma unroll 8
        for (int kk = 0; kk < 64; kk++) {
            float a[4], b[8];
#pragma unroll
            for (int i = 0; i < 4; i++) a[i] = As[kk * KNN_AS_STRIDE + ty * 4 + i];
#pragma unroll
            for (int j = 0; j < 8; j++) b[j] = Bs[kk * KNN_BS_STRIDE + tx * 8 + j];
#pragma unroll
            for (int i = 0; i < 4; i++)
#pragma unroll
                for (int j = 0; j < 8; j++) acc[i][j] = fmaf(a[i], b[j], acc[i][j]);
        }

        // fold this chunk's candidates into running top-4
#pragma unroll
        for (int i = 0; i < 4; i++) {
#pragma unroll
            for (int j = 0; j < 8; j++) {
                int m = m0 + tx * 8 + j;
                float v = Ns[tx * 8 + j] - 2.0f * acc[i][j];
                TOP4_INSERT(v, m, s0[i], x0[i], s1[i], x1[i], s2[i], x2[i], s3[i], x3[i]);
            }
        }
    }

    // Merge 16 per-thread lists per row -> exact top-4 per row.
    __syncthreads();
    float* msc = As;          // 64*64 floats fits in As region
    int* mix = (int*)Bs;      // 64*64 ints fits in Bs region
#pragma unroll
    for (int i = 0; i < 4; i++) {
        int r = ty * 4 + i;
        msc[(r * 16 + tx) * 4 + 0] = s0[i]; mix[(r * 16 + tx) * 4 + 0] = x0[i];
        msc[(r * 16 + tx) * 4 + 1] = s1[i]; mix[(r * 16 + tx) * 4 + 1] = x1[i];
        msc[(r * 16 + tx) * 4 + 2] = s2[i]; mix[(r * 16 + tx) * 4 + 2] = x2[i];
        msc[(r * 16 + tx) * 4 + 3] = s3[i]; mix[(r * 16 + tx) * 4 + 3] = x3[i];
    }
    __syncthreads();
    if (tid < 64) {
        float f0 = FLT_MAX, f1 = FLT_MAX, f2 = FLT_MAX, f3 = FLT_MAX;
        int g0 = 0x7fffffff, g1 = 0x7fffffff, g2 = 0x7fffffff, g3 = 0x7fffffff;
        for (int c = 0; c < 64; c++) {
            float v = msc[tid * 64 + c];
            int m = mix[tid * 64 + c];
            TOP4_INSERT(v, m, f0, g0, f1, g1, f2, g2, f3, g3);
        }
        size_t row = (size_t)h * 1024 + t0 + tid;
        idx_out[row * 4 + 0] = g0;
        idx_out[row * 4 + 1] = g1;
        idx_out[row * 4 + 2] = g2;
        idx_out[row * 4 + 3] = g3;
    }
}

// ---------------- per-token 5-way memory softmax & blend -> v_new ----------------
__device__ __forceinline__ float warp_sum(float v) {
#pragma unroll
    for (int o = 16; o > 0; o >>= 1) v += __shfl_xor_sync(0xffffffffu, v, o);
    return v;
}

__global__ void vnew_kernel(const float* __restrict__ qkv, const float* __restrict__ kstore,
                            const float* __restrict__ vstore, const int* __restrict__ idx,
                            const int* __restrict__ sel, float* __restrict__ vnew) {
    int gw = (blockIdx.x * blockDim.x + threadIdx.x) >> 5;
    int lane = threadIdx.x & 31;
    if (gw >= 16 * 1024) return;
    int h = gw >> 10, t = gw & 1023;

    const float* base = qkv + (size_t)t * 3072 + h * 64;
    int d0 = lane * 2;
    float q0 = base[d0],        q1 = base[d0 + 1];
    float k0 = base[1024 + d0], k1 = base[1024 + d0 + 1];
    float v0 = base[2048 + d0], v1 = base[2048 + d0 + 1];
    const float scale = 0.125f;

    float attf[5];
    attf[0] = warp_sum(q0 * k0 + q1 * k1) * scale;

    int ids[4];
#pragma unroll
    for (int s2 = 0; s2 < 4; s2++) ids[s2] = idx[(size_t)gw * 4 + s2];

    float fv0[4], fv1[4];
#pragma unroll
    for (int s2 = 0; s2 < 4; s2++) {
        const float* kp = kstore + ((size_t)h * 8192 + ids[s2]) * 64;
        attf[s2 + 1] = warp_sum(q0 * kp[d0] + q1 * kp[d0 + 1]) * scale;
        const float* vp = vstore + ((size_t)h * 8192 + ids[s2]) * 64;
        fv0[s2] = vp[d0]; fv1[s2] = vp[d0 + 1];
    }

    float mx = attf[0];
#pragma unroll
    for (int s2 = 1; s2 < 5; s2++) mx = fmaxf(mx, attf[s2]);
    float e[5], sum = 0.f;
#pragma unroll
    for (int s2 = 0; s2 < 5; s2++) { e[s2] = expf(attf[s2] - mx); sum += e[s2]; }
    float inv = 1.f / sum;

    float o0 = e[0] * v0, o1 = e[0] * v1;
#pragma unroll
    for (int s2 = 0; s2 < 4; s2++) { o0 += e[s2 + 1] * fv0[s2]; o1 += e[s2 + 1] * fv1[s2]; }
    o0 = o0 * inv * 0.5f + v0 * 0.5f;   // RESID_FOUND=RESID_CURR=0.5
    o1 = o1 * inv * 0.5f + v1 * 0.5f;

    bool sl = sel[gw] != 0;
    vnew[(size_t)gw * 64 + d0]     = sl ? o0 : v0;
    vnew[(size_t)gw * 64 + d0 + 1] = sl ? o1 : v1;
}

// ---------------- y = att @ v_new  (per head, N=64), writes (T,C) layout ----------------
__global__ void ygemm_kernel(const float* __restrict__ att, const float* __restrict__ vnew,
                             float* __restrict__ y) {
    int h = blockIdx.y, t0 = blockIdx.x * 128;
    __shared__ float As[16][132];  // [k][t], padded
    __shared__ float Bs[16][64];   // [k][dd]
    int tid = threadIdx.x;
    int tx = tid & 7, ty = tid >> 3;  // tx: 8 groups of 8 dd; ty: 32 groups of 4 t

    float acc[4][8];
#pragma unroll
    for (int i = 0; i < 4; i++)
#pragma unroll
        for (int j = 0; j < 8; j++) acc[i][j] = 0.f;

    const float* Ab = att + ((size_t)h * 1024 + t0) * 1024;
    const float* Bb = vnew + (size_t)h * 1024 * 64;

    int r = tid >> 2, c = (tid & 3) * 4;          // att loader
    int rb = tid >> 4, cb = (tid & 15) * 4;       // vnew loader

    for (int k0 = 0; k0 < 1024; k0 += 16) {
        float4 fa0 = *(const float4*)(Ab + (size_t)r * 1024 + k0 + c);
        float4 fa1 = *(const float4*)(Ab + (size_t)(r + 64) * 1024 + k0 + c);
        float4 fb  = *(const float4*)(Bb + (size_t)(k0 + rb) * 64 + cb);
        __syncthreads();
        As[c + 0][r] = fa0.x; As[c + 1][r] = fa0.y; As[c + 2][r] = fa0.z; As[c + 3][r] = fa0.w;
        As[c + 0][r + 64] = fa1.x; As[c + 1][r + 64] = fa1.y;
        As[c + 2][r + 64] = fa1.z; As[c + 3][r + 64] = fa1.w;
        *(float4*)&Bs[rb][cb] = fb;
        __syncthreads();
#pragma unroll
        for (int kk = 0; kk < 16; kk++) {
            float a[4], b[8];
#pragma unroll
            for (int i = 0; i < 4; i++) a[i] = As[kk][ty * 4 + i];
#pragma unroll
            for (int j = 0; j < 8; j++) b[j] = Bs[kk][tx * 8 + j];
#pragma unroll
            for (int i = 0; i < 4; i++)
#pragma unroll
                for (int j = 0; j < 8; j++) acc[i][j] = fmaf(a[i], b[j], acc[i][j]);
        }
    }

#pragma unroll
    for (int i = 0; i < 4; i++)
#pragma unroll
        for (int j = 0; j < 8; j++)
            y[(size_t)(t0 + ty * 4 + i) * 1024 + h * 64 + tx * 8 + j] = acc[i][j];
}

// ---------------- launch ----------------
extern "C" void kernel_launch(void* const* d_in, const int* in_sizes, int n_in,
                              void* d_out, int out_size) {
    const float* x  = (const float*)d_in[0];
    const float* aw = (const float*)d_in[1];
    const float* ab = (const float*)d_in[2];
    const float* pw = (const float*)d_in[3];
    const float* pb = (const float*)d_in[4];
    const float* ks = (const float*)d_in[5];
    const float* vs = (const float*)d_in[6];
    float* out = (float*)d_out;

    float *qkv, *att, *ksn, *vnw, *y;
    int *idx, *sel;
    cudaGetSymbolAddress((void**)&qkv,    g_qkv);
    cudaGetSymbolAddress((void**)&att,    g_att);
    cudaGetSymbolAddress((void**)&ksn,    g_ksnorm);
    cudaGetSymbolAddress((void**)&idx,    g_idx);
    cudaGetSymbolAddress((void**)&sel,    g_sel);
    cudaGetSymbolAddress((void**)&vnw,    g_vnew);
    cudaGetSymbolAddress((void**)&y,      g_y);

    // allow >48KB dynamic smem for the fused kNN kernel (idempotent, capturable)
    cudaFuncSetAttribute(knn_topk_kernel,
                         cudaFuncAttributeMaxDynamicSharedMemorySize,
                         KNN_SMEM_FLOATS * (int)sizeof(float));

    // 1) qkv = x @ c_attn_w^T + b    (M=1024, N=3072, K=1024)
    gemm128<0><<<dim3(24, 8, 1), 256>>>(x, 1024, 0, aw, 1024, 0,
                                        qkv, 3072, 0, 1024, ab, 0);
    // 2) ||key_store||^2 per (h,m)
    ksnorm_kernel<<<512, 256>>>(ks, ksn);
    // 3) logits = q k^T / 8  (per head, causal tiles only)
    gemm128<1><<<dim3(8, 8, 16), 256>>>(qkv, 3072, 64, qkv + 1024, 3072, 64,
                                        att, 1024, 1024LL * 1024, 64, nullptr, 0);
    // 4) causal softmax in place
    softmax_kernel<<<dim3(1024, 16), 256>>>(att);
    // 5) sel from last row
    sel_kernel<<<64, 256>>>(att, sel);
    // 6+7) fused kNN scores + top-4 (no scores materialization)
    knn_topk_kernel<<<dim3(16, 16), 256, KNN_SMEM_FLOATS * sizeof(float)>>>(
        qkv, ks, ksn, idx);
    // 8) 5-way softmax blend -> v_new
    vnew_kernel<<<2048, 256>>>(qkv, ks, vs, idx, sel, vnw);
    // 9) y = att @ v_new (per head), (T,C) layout
    ygemm_kernel<<<dim3(8, 16), 256>>>(att, vnw, y);
    // 10) out = y @ c_proj_w^T + b
    gemm128<0><<<dim3(8, 8, 1), 256>>>(y, 1024, 0, pw, 1024, 0,
                                       out, 1024, 0, 1024, pb, 0);
}